// round 9
// baseline (speedup 1.0000x reference)
#include <cuda_runtime.h>
#include <math.h>
#include <stdint.h>

#define NN   40960
#define SS   4096
#define EE   81920
#define DD   64
#define HH   100
#define FIN  321
#define VV   50000

// ---------------- scratch (device globals; no allocation allowed) ----------------
__device__ float    g_x[NN * FIN];
__device__ float    g_xl[SS * FIN];
__device__ float    g_h[NN * HH];
__device__ float    g_msg[NN * HH];
__device__ float    g_gi[NN * 3 * HH];
__device__ float    g_gh[NN * 3 * HH];
__device__ int      g_deg[NN];
__device__ float    g_dinv[NN];
__device__ int      g_lastidx[SS];
__device__ float    g_last[SS * HH];
__device__ float    g_g1[NN * HH];
__device__ float    g_gate[NN];
__device__ float    g_w[NN];
__device__ unsigned g_gmax[SS];
__device__ float    g_wsum[SS];
__device__ float    g_pooled[SS * HH];

// ---------------- f32x2 packed-math helpers (Blackwell FFMA2) ----------------
__device__ __forceinline__ unsigned long long f2_pack(float lo, float hi) {
    unsigned long long r;
    asm("mov.b64 %0, {%1, %2};" : "=l"(r) : "f"(lo), "f"(hi));
    return r;
}
__device__ __forceinline__ float2 f2_unpack(unsigned long long v) {
    float lo, hi;
    asm("mov.b64 {%0, %1}, %2;" : "=f"(lo), "=f"(hi) : "l"(v));
    return make_float2(lo, hi);
}
__device__ __forceinline__ unsigned long long f2_fma(unsigned long long a,
                                                     unsigned long long b,
                                                     unsigned long long c) {
    asm("fma.rn.f32x2 %0, %1, %2, %3;" : "=l"(c) : "l"(a), "l"(b), "l"(c));
    return c;
}

// ---------------- tf32 helpers (legacy mma.sync path: plain sm_80+ PTX) ----------------
__device__ __forceinline__ float to_tf32(float x) {
    float r;
    asm("cvt.rna.tf32.f32 %0, %1;" : "=f"(r) : "f"(x));
    return r;
}
__device__ __forceinline__ void mma_16n8k8(float* d,
                                           const uint32_t* a, const uint32_t* b) {
    asm volatile(
        "mma.sync.aligned.m16n8k8.row.col.f32.tf32.tf32.f32 "
        "{%0, %1, %2, %3}, {%4, %5, %6, %7}, {%8, %9}, {%0, %1, %2, %3};"
        : "+f"(d[0]), "+f"(d[1]), "+f"(d[2]), "+f"(d[3])
        : "r"(a[0]), "r"(a[1]), "r"(a[2]), "r"(a[3]), "r"(b[0]), "r"(b[1]));
}

// ---------------- helpers ----------------
__device__ __forceinline__ unsigned enc_f(float f) {
    unsigned u = __float_as_uint(f);
    return (u & 0x80000000u) ? ~u : (u | 0x80000000u);
}
__device__ __forceinline__ float dec_f(unsigned e) {
    return (e & 0x80000000u) ? __uint_as_float(e ^ 0x80000000u) : __uint_as_float(~e);
}

// ---------------- init / zero ----------------
__global__ void k_init_small() {
    int i = blockIdx.x * blockDim.x + threadIdx.x;
    if (i < NN) g_deg[i] = 0;
    if (i < SS) { g_lastidx[i] = -1; g_gmax[i] = 0u; g_wsum[i] = 0.f; }
}
__global__ void k_zero_big() {
    int i = blockIdx.x * blockDim.x + threadIdx.x;
    if (i < NN * HH) g_msg[i] = 0.f;
    if (i < SS * HH) g_pooled[i] = 0.f;
}

// ---------------- node feature gather: x[n, 0..320] ----------------
__global__ void k_gather_x(const float* __restrict__ price,
                           const int* __restrict__ cat, const int* __restrict__ sub,
                           const int* __restrict__ elem, const int* __restrict__ brand,
                           const int* __restrict__ pid,
                           const float* __restrict__ ecat, const float* __restrict__ esub,
                           const float* __restrict__ eelem, const float* __restrict__ ebrand,
                           const float* __restrict__ eitem) {
    int n = blockIdx.x;
    int j = threadIdx.x;
    if (j >= FIN) return;
    float v;
    if (j == 0) {
        v = price[n];
    } else {
        int s = (j - 1) >> 6;
        int o = (j - 1) & 63;
        const float* tab;
        int idx;
        switch (s) {
            case 0:  tab = ecat;   idx = cat[n];   break;
            case 1:  tab = esub;   idx = sub[n];   break;
            case 2:  tab = eelem;  idx = elem[n];  break;
            case 3:  tab = ebrand; idx = brand[n]; break;
            default: tab = eitem;  idx = pid[n];   break;
        }
        v = tab[idx * DD + o];
    }
    g_x[n * FIN + j] = v;
}

// ---------------- tiled SGEMM: C = A[M,K] @ B[K,Nn] + bias, optional relu ----------------
// 128x64 block tile, 8x4 per-thread register tile, f32x2 packed FMA.
__global__ void k_sgemm(const float* __restrict__ A, const float* __restrict__ B,
                        const float* __restrict__ bias, float* __restrict__ C,
                        int M, int Nn, int K, int relu) {
    __shared__ float As[128][17];
    __shared__ float Bs[16][64];
    int tid = threadIdx.x;
    int tx = tid & 15, ty = tid >> 4;     // tx: 4 cols each, ty: 8 rows each
    int m0 = blockIdx.y * 128, n0 = blockIdx.x * 64;

    unsigned long long acc2[8][2];
#pragma unroll
    for (int i = 0; i < 8; i++) { acc2[i][0] = 0ull; acc2[i][1] = 0ull; }

    for (int k0 = 0; k0 < K; k0 += 16) {
        for (int i = tid; i < 128 * 16; i += 256) {
            int mi = i >> 4, ki = i & 15;
            int m = m0 + mi, k = k0 + ki;
            As[mi][ki] = (m < M && k < K) ? A[m * K + k] : 0.f;
        }
        for (int i = tid; i < 16 * 64; i += 256) {
            int ki = i >> 6, ni = i & 63;
            int k = k0 + ki, n = n0 + ni;
            Bs[ki][ni] = (k < K && n < Nn) ? B[k * Nn + n] : 0.f;
        }
        __syncthreads();
#pragma unroll
        for (int k = 0; k < 16; k++) {
            ulonglong2 b2 = *(const ulonglong2*)&Bs[k][tx * 4];
#pragma unroll
            for (int i = 0; i < 8; i++) {
                float a = As[ty * 8 + i][k];
                unsigned long long ap = f2_pack(a, a);
                acc2[i][0] = f2_fma(ap, b2.x, acc2[i][0]);
                acc2[i][1] = f2_fma(ap, b2.y, acc2[i][1]);
            }
        }
        __syncthreads();
    }

#pragma unroll
    for (int i = 0; i < 8; i++) {
        int m = m0 + ty * 8 + i;
        if (m >= M) continue;
        float2 p0 = f2_unpack(acc2[i][0]);
        float2 p1 = f2_unpack(acc2[i][1]);
        float vals[4] = {p0.x, p0.y, p1.x, p1.y};
#pragma unroll
        for (int j = 0; j < 4; j++) {
            int n = n0 + tx * 4 + j;
            if (n >= Nn) continue;
            float v = vals[j] + bias[n];
            if (relu) v = fmaxf(v, 0.f);
            C[m * Nn + n] = v;
        }
    }
}

// ---------------- degree + inverse ----------------
__global__ void k_deg(const int* __restrict__ eidx) {
    int e = blockIdx.x * blockDim.x + threadIdx.x;
    if (e < EE) atomicAdd(&g_deg[eidx[EE + e]], 1);
}
__global__ void k_dinv() {
    int n = blockIdx.x * blockDim.x + threadIdx.x;
    if (n < NN) g_dinv[n] = (g_deg[n] > 0) ? (1.f / (float)g_deg[n]) : 0.f;
}

// ---------------- edge scatter: msg[dst] += h[src] ----------------
__global__ void k_scatter(const int* __restrict__ eidx) {
    int e = blockIdx.x;
    int d = threadIdx.x;
    if (d >= HH) return;
    int s = eidx[e];
    int t = eidx[EE + e];
    atomicAdd(&g_msg[t * HH + d], g_h[s * HH + d]);
}
__global__ void k_scale_msg() {
    int i = blockIdx.x * blockDim.x + threadIdx.x;
    if (i < NN * HH) g_msg[i] *= g_dinv[i / HH];
}

// ---------------- GRU cell elementwise ----------------
__global__ void k_gru() {
    int i = blockIdx.x * blockDim.x + threadIdx.x;
    if (i >= NN * HH) return;
    int n = i / HH, j = i % HH;
    const float* gi = g_gi + n * 3 * HH;
    const float* gh = g_gh + n * 3 * HH;
    float r  = 1.f / (1.f + expf(-(gi[j] + gh[j])));
    float z  = 1.f / (1.f + expf(-(gi[HH + j] + gh[HH + j])));
    float nn = tanhf(gi[2 * HH + j] + r * gh[2 * HH + j]);
    float h  = g_h[i];
    g_h[i] = (1.f - z) * nn + z * h;
}

// ---------------- last index per session + gather ----------------
__global__ void k_lastidx(const int* __restrict__ batch) {
    int n = blockIdx.x * blockDim.x + threadIdx.x;
    if (n < NN) atomicMax(&g_lastidx[batch[n]], n);
}
__global__ void k_gather_xl() {
    int s = blockIdx.x;
    int j = threadIdx.x;
    if (j >= FIN) return;
    g_xl[s * FIN + j] = g_x[g_lastidx[s] * FIN + j];
}
__global__ void k_addlast(const int* __restrict__ batch) {
    int i = blockIdx.x * blockDim.x + threadIdx.x;
    if (i >= NN * HH) return;
    g_h[i] += g_last[batch[i / HH] * HH + i % HH];
}

// ---------------- attention gate ----------------
__global__ void k_gate(const float* __restrict__ wg2, const float* __restrict__ bg2,
                       const int* __restrict__ batch) {
    int w = (blockIdx.x * blockDim.x + threadIdx.x) >> 5;
    int lane = threadIdx.x & 31;
    if (w >= NN) return;
    const float* row = g_g1 + w * HH;
    float s = 0.f;
    for (int k = lane; k < HH; k += 32) s += row[k] * wg2[k];
#pragma unroll
    for (int o = 16; o; o >>= 1) s += __shfl_xor_sync(0xffffffffu, s, o);
    if (lane == 0) {
        float g = s + bg2[0];
        g_gate[w] = g;
        atomicMax(&g_gmax[batch[w]], enc_f(g));
    }
}
__global__ void k_softw(const int* __restrict__ batch) {
    int n = blockIdx.x * blockDim.x + threadIdx.x;
    if (n >= NN) return;
    int b = batch[n];
    float wv = expf(g_gate[n] - dec_f(g_gmax[b]));
    g_w[n] = wv;
    atomicAdd(&g_wsum[b], wv);
}
__global__ void k_pool(const int* __restrict__ batch) {
    int n = blockIdx.x;
    int d = threadIdx.x;
    if (d >= HH) return;
    int b = batch[n];
    float alpha = g_w[n] / g_wsum[b];
    atomicAdd(&g_pooled[b * HH + d], alpha * g_h[n * HH + d]);
}

// ================= FC via legacy tensor-core mma.sync (tf32, HMMA path) =================
// out[4096,50000] = pooled @ W_fc + b_fc
// CTA: N-tile 128 cols, 16 M-tiles of 128 rows. grid (391, 2).
// Bs[n][k] (128 x 105, transposed for .col B operand) resident for whole K.
// As[r][k] (128 x 105) reloaded per M-tile. Warp grid 2x4; warp tile 64x32:
// 4x4 m16n8k8 MMAs per 8-wide k-step, 13 k-steps (K padded 100->104 with zeros).
// Fragment layout per PTX spec (m16n8k8 tf32):
//   A: a0=(g,tg) a1=(g+8,tg) a2=(g,tg+4) a3=(g+8,tg+4)
//   B: b0=(k=tg,n=g) b1=(k=tg+4,n=g)
//   C: c0/c1=(g, 2tg/2tg+1) c2/c3=(g+8, 2tg/2tg+1)
#define FKP 105                       // padded k-stride (105 mod 32 = 9, conflict-free)
#define FC_SMEM_MMA ((2 * 128 * FKP + 128) * 4)

__global__ void __launch_bounds__(256, 1)
k_fc(const float* __restrict__ pooled, const float* __restrict__ W,
     const float* __restrict__ bias, float* __restrict__ C) {
    extern __shared__ float sm[];
    float* Bs    = sm;                  // [128][FKP]
    float* As    = sm + 128 * FKP;      // [128][FKP]
    float* biasS = sm + 2 * 128 * FKP;  // [128]
    int tid = threadIdx.x;
    int lane = tid & 31, wid = tid >> 5;
    int n0 = blockIdx.x * 128;
    int m_begin = blockIdx.y * 16;      // 16 M-tiles per CTA

    // zero tiles (covers K-pad cols and out-of-range N rows)
    for (int i = tid; i < 2 * 128 * FKP; i += 256) sm[i] = 0.f;
    if (tid < 128) biasS[tid] = (n0 + tid < VV) ? bias[n0 + tid] : 0.f;
    __syncthreads();

    // load B panel: W[k][n] -> Bs[n][k], coalesced over n
    for (int i = tid; i < HH * 128; i += 256) {
        int k = i >> 7, n = i & 127;
        int gn = n0 + n;
        if (gn < VV) Bs[n * FKP + k] = to_tf32(W[(size_t)k * VV + gn]);
    }

    int wm = wid >> 2, wn = wid & 3;    // warp tile: rows wm*64, cols wn*32
    int g = lane >> 2, tg = lane & 3;   // fragment group / thread-in-group

    for (int it = 0; it < 16; it++) {
        int m0 = (m_begin + it) * 128;
        for (int i = tid; i < 128 * HH; i += 256) {
            int r = i / HH, k = i - r * HH;
            As[r * FKP + k] = to_tf32(pooled[(m0 + r) * HH + k]);
        }
        __syncthreads();

        float acc[4][4][4];
#pragma unroll
        for (int mi = 0; mi < 4; mi++)
#pragma unroll
            for (int ni = 0; ni < 4; ni++)
#pragma unroll
                for (int j = 0; j < 4; j++) acc[mi][ni][j] = 0.f;

        for (int ks = 0; ks < 13; ks++) {
            int kb = ks * 8;
            uint32_t af[4][4], bf[4][2];
#pragma unroll
            for (int mi = 0; mi < 4; mi++) {
                const float* ap = &As[(wm * 64 + mi * 16 + g) * FKP + kb + tg];
                af[mi][0] = __float_as_uint(ap[0]);            // (g,     tg)
                af[mi][1] = __float_as_uint(ap[8 * FKP]);      // (g + 8, tg)
                af[mi][2] = __float_as_uint(ap[4]);            // (g,     tg + 4)
                af[mi][3] = __float_as_uint(ap[8 * FKP + 4]);  // (g + 8, tg + 4)
            }
#pragma unroll
            for (int ni = 0; ni < 4; ni++) {
                const float* bp = &Bs[(wn * 32 + ni * 8 + g) * FKP + kb + tg];
                bf[ni][0] = __float_as_uint(bp[0]);
                bf[ni][1] = __float_as_uint(bp[4]);
            }
#pragma unroll
            for (int mi = 0; mi < 4; mi++)
#pragma unroll
                for (int ni = 0; ni < 4; ni++)
                    mma_16n8k8(acc[mi][ni], af[mi], bf[ni]);
        }

        // epilogue: c0/c1 at (row, 2tg), c2/c3 at (row+8, 2tg)
#pragma unroll
        for (int mi = 0; mi < 4; mi++) {
            int r = m0 + wm * 64 + mi * 16 + g;
            size_t rb0 = (size_t)r * VV;
            size_t rb1 = (size_t)(r + 8) * VV;
#pragma unroll
            for (int ni = 0; ni < 4; ni++) {
                int cn = wn * 32 + ni * 8 + 2 * tg;
                int gn = n0 + cn;
                if (gn < VV) {   // VV even, gn even -> pair fully in range
                    float bx = biasS[cn], by = biasS[cn + 1];
                    *(float2*)&C[rb0 + gn] = make_float2(acc[mi][ni][0] + bx,
                                                         acc[mi][ni][1] + by);
                    *(float2*)&C[rb1 + gn] = make_float2(acc[mi][ni][2] + bx,
                                                         acc[mi][ni][3] + by);
                }
            }
        }
        __syncthreads();
    }
}

// ---------------- launch ----------------
extern "C" void kernel_launch(void* const* d_in, const int* in_sizes, int n_in,
                              void* d_out, int out_size) {
    const float* price    = (const float*)d_in[0];
    const int*   category = (const int*)d_in[1];
    const int*   sub      = (const int*)d_in[2];
    const int*   elem     = (const int*)d_in[3];
    const int*   brand    = (const int*)d_in[4];
    const int*   pid      = (const int*)d_in[5];
    const int*   eidx     = (const int*)d_in[6];
    const int*   batch    = (const int*)d_in[7];
    const float* ecat     = (const float*)d_in[8];
    const float* esub     = (const float*)d_in[9];
    const float* eelem    = (const float*)d_in[10];
    const float* ebrand   = (const float*)d_in[11];
    const float* eitem    = (const float*)d_in[12];
    const float* W_msg    = (const float*)d_in[13];
    const float* b_msg    = (const float*)d_in[14];
    const float* W_ih     = (const float*)d_in[15];
    const float* W_hh     = (const float*)d_in[16];
    const float* b_ih     = (const float*)d_in[17];
    const float* b_hh     = (const float*)d_in[18];
    const float* W_last   = (const float*)d_in[19];
    const float* b_last   = (const float*)d_in[20];
    const float* W_g1     = (const float*)d_in[21];
    const float* b_g1     = (const float*)d_in[22];
    const float* W_g2     = (const float*)d_in[23];
    const float* b_g2     = (const float*)d_in[24];
    const float* W_fc     = (const float*)d_in[25];
    const float* b_fc     = (const float*)d_in[26];
    float* out = (float*)d_out;

    float *p_x, *p_xl, *p_h, *p_msg, *p_gi, *p_gh, *p_last, *p_g1, *p_pooled;
    cudaGetSymbolAddress((void**)&p_x,      g_x);
    cudaGetSymbolAddress((void**)&p_xl,     g_xl);
    cudaGetSymbolAddress((void**)&p_h,      g_h);
    cudaGetSymbolAddress((void**)&p_msg,    g_msg);
    cudaGetSymbolAddress((void**)&p_gi,     g_gi);
    cudaGetSymbolAddress((void**)&p_gh,     g_gh);
    cudaGetSymbolAddress((void**)&p_last,   g_last);
    cudaGetSymbolAddress((void**)&p_g1,     g_g1);
    cudaGetSymbolAddress((void**)&p_pooled, g_pooled);

    cudaFuncSetAttribute(k_fc, cudaFuncAttributeMaxDynamicSharedMemorySize, FC_SMEM_MMA);

    // init scratch
    k_init_small<<<(NN + 255) / 256, 256>>>();
    k_zero_big<<<(NN * HH + 255) / 256, 256>>>();

    // node features
    k_gather_x<<<NN, 352>>>(price, category, sub, elem, brand, pid,
                            ecat, esub, eelem, ebrand, eitem);

    // h0 = x @ W_msg + b_msg
    {
        dim3 g((HH + 63) / 64, (NN + 127) / 128);
        k_sgemm<<<g, 256>>>(p_x, W_msg, b_msg, p_h, NN, HH, FIN, 0);
    }

    // degrees
    k_deg<<<(EE + 255) / 256, 256>>>(eidx);
    k_dinv<<<(NN + 255) / 256, 256>>>();

    // mean aggregation
    k_scatter<<<EE, 128>>>(eidx);
    k_scale_msg<<<(NN * HH + 255) / 256, 256>>>();

    // GRU gates
    {
        dim3 g((3 * HH + 63) / 64, (NN + 127) / 128);
        k_sgemm<<<g, 256>>>(p_msg, W_ih, b_ih, p_gi, NN, 3 * HH, HH, 0);
        k_sgemm<<<g, 256>>>(p_h,   W_hh, b_hh, p_gh, NN, 3 * HH, HH, 0);
    }
    k_gru<<<(NN * HH + 255) / 256, 256>>>();

    // last node per session
    k_lastidx<<<(NN + 255) / 256, 256>>>(batch);
    k_gather_xl<<<SS, 352>>>();
    {
        dim3 g((HH + 63) / 64, (SS + 127) / 128);
        k_sgemm<<<g, 256>>>(p_xl, W_last, b_last, p_last, SS, HH, FIN, 0);
    }
    k_addlast<<<(NN * HH + 255) / 256, 256>>>(batch);

    // attention gate MLP
    {
        dim3 g((HH + 63) / 64, (NN + 127) / 128);
        k_sgemm<<<g, 256>>>(p_h, W_g1, b_g1, p_g1, NN, HH, HH, 1);
    }
    k_gate<<<(NN * 32 + 255) / 256, 256>>>(W_g2, b_g2, batch);
    k_softw<<<(NN + 255) / 256, 256>>>(batch);
    k_pool<<<NN, 128>>>(batch);

    // final scoring: legacy tensor-core mma.sync tf32
    {
        dim3 g((VV + 127) / 128, 2);
        k_fc<<<g, 256, FC_SMEM_MMA>>>(p_pooled, W_fc, b_fc, out);
    }
}

// round 10
// speedup vs baseline: 1.6402x; 1.6402x over previous
#include <cuda_runtime.h>
#include <cuda_fp16.h>
#include <math.h>
#include <stdint.h>

#define NN   40960
#define SS   4096
#define EE   81920
#define DD   64
#define HH   100
#define FIN  321
#define VV   50000

// ---------------- scratch (device globals; no allocation allowed) ----------------
__device__ float    g_x[NN * FIN];
__device__ float    g_xl[SS * FIN];
__device__ float    g_h[NN * HH];
__device__ float    g_msg[NN * HH];
__device__ float    g_gi[NN * 3 * HH];
__device__ float    g_gh[NN * 3 * HH];
__device__ int      g_deg[NN];
__device__ float    g_dinv[NN];
__device__ int      g_lastidx[SS];
__device__ float    g_last[SS * HH];
__device__ float    g_g1[NN * HH];
__device__ float    g_gate[NN];
__device__ float    g_w[NN];
__device__ unsigned g_gmax[SS];
__device__ float    g_wsum[SS];
__device__ float    g_pooled[SS * HH];

// ---------------- f32x2 packed-math helpers (Blackwell FFMA2) ----------------
__device__ __forceinline__ unsigned long long f2_pack(float lo, float hi) {
    unsigned long long r;
    asm("mov.b64 %0, {%1, %2};" : "=l"(r) : "f"(lo), "f"(hi));
    return r;
}
__device__ __forceinline__ float2 f2_unpack(unsigned long long v) {
    float lo, hi;
    asm("mov.b64 {%0, %1}, %2;" : "=f"(lo), "=f"(hi) : "l"(v));
    return make_float2(lo, hi);
}
__device__ __forceinline__ unsigned long long f2_fma(unsigned long long a,
                                                     unsigned long long b,
                                                     unsigned long long c) {
    asm("fma.rn.f32x2 %0, %1, %2, %3;" : "=l"(c) : "l"(a), "l"(b), "l"(c));
    return c;
}

// ---------------- fp16 mma.sync (plain HMMA path, sm_70+ PTX) ----------------
// m16n8k16 row.col f32.f16.f16.f32 fragment layout (g = lane>>2, tg = lane&3):
//   A reg0 = (row g,   k 2tg..2tg+1)   reg1 = (row g+8, k 2tg..2tg+1)
//   A reg2 = (row g,   k 2tg+8..+9)    reg3 = (row g+8, k 2tg+8..+9)
//   B reg0 = (k 2tg..2tg+1, col g)     reg1 = (k 2tg+8..+9, col g)
//   C c0/c1 = (row g, col 2tg/2tg+1)   c2/c3 = (row g+8, same cols)
__device__ __forceinline__ void mma_16n8k16_f16(float* d,
                                                const uint32_t* a, const uint32_t* b) {
    asm volatile(
        "mma.sync.aligned.m16n8k16.row.col.f32.f16.f16.f32 "
        "{%0, %1, %2, %3}, {%4, %5, %6, %7}, {%8, %9}, {%0, %1, %2, %3};"
        : "+f"(d[0]), "+f"(d[1]), "+f"(d[2]), "+f"(d[3])
        : "r"(a[0]), "r"(a[1]), "r"(a[2]), "r"(a[3]), "r"(b[0]), "r"(b[1]));
}

// ---------------- helpers ----------------
__device__ __forceinline__ unsigned enc_f(float f) {
    unsigned u = __float_as_uint(f);
    return (u & 0x80000000u) ? ~u : (u | 0x80000000u);
}
__device__ __forceinline__ float dec_f(unsigned e) {
    return (e & 0x80000000u) ? __uint_as_float(e ^ 0x80000000u) : __uint_as_float(~e);
}
__device__ __forceinline__ float fast_sigmoid(float x) {
    return 1.f / (1.f + __expf(-x));
}
__device__ __forceinline__ float fast_tanh(float x) {
    float t = __expf(-2.f * fabsf(x));
    float y = (1.f - t) / (1.f + t);
    return copysignf(y, x);
}

// ---------------- init / zero ----------------
__global__ void k_init_small() {
    int i = blockIdx.x * blockDim.x + threadIdx.x;
    if (i < NN) g_deg[i] = 0;
    if (i < SS) { g_lastidx[i] = -1; g_gmax[i] = 0u; g_wsum[i] = 0.f; }
}
__global__ void k_zero_big() {
    int i = blockIdx.x * blockDim.x + threadIdx.x;
    if (i < NN * HH) g_msg[i] = 0.f;
    if (i < SS * HH) g_pooled[i] = 0.f;
}

// ---------------- node feature gather: x[n, 0..320] ----------------
__global__ void k_gather_x(const float* __restrict__ price,
                           const int* __restrict__ cat, const int* __restrict__ sub,
                           const int* __restrict__ elem, const int* __restrict__ brand,
                           const int* __restrict__ pid,
                           const float* __restrict__ ecat, const float* __restrict__ esub,
                           const float* __restrict__ eelem, const float* __restrict__ ebrand,
                           const float* __restrict__ eitem) {
    int n = blockIdx.x;
    int j = threadIdx.x;
    if (j >= FIN) return;
    float v;
    if (j == 0) {
        v = price[n];
    } else {
        int s = (j - 1) >> 6;
        int o = (j - 1) & 63;
        const float* tab;
        int idx;
        switch (s) {
            case 0:  tab = ecat;   idx = cat[n];   break;
            case 1:  tab = esub;   idx = sub[n];   break;
            case 2:  tab = eelem;  idx = elem[n];  break;
            case 3:  tab = ebrand; idx = brand[n]; break;
            default: tab = eitem;  idx = pid[n];   break;
        }
        v = tab[idx * DD + o];
    }
    g_x[n * FIN + j] = v;
}

// ---------------- tiled SGEMM: C = A[M,K] @ B[K,Nn] + bias, optional relu ----------------
// 128x64 block tile, 8x4 per-thread register tile, f32x2 packed FMA.
__global__ void k_sgemm(const float* __restrict__ A, const float* __restrict__ B,
                        const float* __restrict__ bias, float* __restrict__ C,
                        int M, int Nn, int K, int relu) {
    __shared__ float As[128][17];
    __shared__ float Bs[16][64];
    int tid = threadIdx.x;
    int tx = tid & 15, ty = tid >> 4;     // tx: 4 cols each, ty: 8 rows each
    int m0 = blockIdx.y * 128, n0 = blockIdx.x * 64;

    unsigned long long acc2[8][2];
#pragma unroll
    for (int i = 0; i < 8; i++) { acc2[i][0] = 0ull; acc2[i][1] = 0ull; }

    for (int k0 = 0; k0 < K; k0 += 16) {
        for (int i = tid; i < 128 * 16; i += 256) {
            int mi = i >> 4, ki = i & 15;
            int m = m0 + mi, k = k0 + ki;
            As[mi][ki] = (m < M && k < K) ? A[m * K + k] : 0.f;
        }
        for (int i = tid; i < 16 * 64; i += 256) {
            int ki = i >> 6, ni = i & 63;
            int k = k0 + ki, n = n0 + ni;
            Bs[ki][ni] = (k < K && n < Nn) ? B[k * Nn + n] : 0.f;
        }
        __syncthreads();
#pragma unroll
        for (int k = 0; k < 16; k++) {
            ulonglong2 b2 = *(const ulonglong2*)&Bs[k][tx * 4];
#pragma unroll
            for (int i = 0; i < 8; i++) {
                float a = As[ty * 8 + i][k];
                unsigned long long ap = f2_pack(a, a);
                acc2[i][0] = f2_fma(ap, b2.x, acc2[i][0]);
                acc2[i][1] = f2_fma(ap, b2.y, acc2[i][1]);
            }
        }
        __syncthreads();
    }

#pragma unroll
    for (int i = 0; i < 8; i++) {
        int m = m0 + ty * 8 + i;
        if (m >= M) continue;
        float2 p0 = f2_unpack(acc2[i][0]);
        float2 p1 = f2_unpack(acc2[i][1]);
        float vals[4] = {p0.x, p0.y, p1.x, p1.y};
#pragma unroll
        for (int j = 0; j < 4; j++) {
            int n = n0 + tx * 4 + j;
            if (n >= Nn) continue;
            float v = vals[j] + bias[n];
            if (relu) v = fmaxf(v, 0.f);
            C[m * Nn + n] = v;
        }
    }
}

// ---------------- degree + inverse ----------------
__global__ void k_deg(const int* __restrict__ eidx) {
    int e = blockIdx.x * blockDim.x + threadIdx.x;
    if (e < EE) atomicAdd(&g_deg[eidx[EE + e]], 1);
}
__global__ void k_dinv() {
    int n = blockIdx.x * blockDim.x + threadIdx.x;
    if (n < NN) g_dinv[n] = (g_deg[n] > 0) ? (1.f / (float)g_deg[n]) : 0.f;
}

// ---------------- edge scatter: msg[dst] += h[src] ----------------
__global__ void k_scatter(const int* __restrict__ eidx) {
    int e = blockIdx.x;
    int d = threadIdx.x;
    if (d >= HH) return;
    int s = eidx[e];
    int t = eidx[EE + e];
    atomicAdd(&g_msg[t * HH + d], g_h[s * HH + d]);
}
__global__ void k_scale_msg() {
    int i = blockIdx.x * blockDim.x + threadIdx.x;
    if (i < NN * HH) g_msg[i] *= g_dinv[i / HH];
}

// ---------------- GRU cell elementwise ----------------
__global__ void k_gru() {
    int i = blockIdx.x * blockDim.x + threadIdx.x;
    if (i >= NN * HH) return;
    int n = i / HH, j = i % HH;
    const float* gi = g_gi + n * 3 * HH;
    const float* gh = g_gh + n * 3 * HH;
    float r  = fast_sigmoid(gi[j] + gh[j]);
    float z  = fast_sigmoid(gi[HH + j] + gh[HH + j]);
    float nn = fast_tanh(gi[2 * HH + j] + r * gh[2 * HH + j]);
    float h  = g_h[i];
    g_h[i] = (1.f - z) * nn + z * h;
}

// ---------------- last index per session + gather ----------------
__global__ void k_lastidx(const int* __restrict__ batch) {
    int n = blockIdx.x * blockDim.x + threadIdx.x;
    if (n < NN) atomicMax(&g_lastidx[batch[n]], n);
}
__global__ void k_gather_xl() {
    int s = blockIdx.x;
    int j = threadIdx.x;
    if (j >= FIN) return;
    g_xl[s * FIN + j] = g_x[g_lastidx[s] * FIN + j];
}
__global__ void k_addlast(const int* __restrict__ batch) {
    int i = blockIdx.x * blockDim.x + threadIdx.x;
    if (i >= NN * HH) return;
    g_h[i] += g_last[batch[i / HH] * HH + i % HH];
}

// ---------------- attention gate ----------------
__global__ void k_gate(const float* __restrict__ wg2, const float* __restrict__ bg2,
                       const int* __restrict__ batch) {
    int w = (blockIdx.x * blockDim.x + threadIdx.x) >> 5;
    int lane = threadIdx.x & 31;
    if (w >= NN) return;
    const float* row = g_g1 + w * HH;
    float s = 0.f;
    for (int k = lane; k < HH; k += 32) s += row[k] * wg2[k];
#pragma unroll
    for (int o = 16; o; o >>= 1) s += __shfl_xor_sync(0xffffffffu, s, o);
    if (lane == 0) {
        float g = s + bg2[0];
        g_gate[w] = g;
        atomicMax(&g_gmax[batch[w]], enc_f(g));
    }
}
__global__ void k_softw(const int* __restrict__ batch) {
    int n = blockIdx.x * blockDim.x + threadIdx.x;
    if (n >= NN) return;
    int b = batch[n];
    float wv = __expf(g_gate[n] - dec_f(g_gmax[b]));
    g_w[n] = wv;
    atomicAdd(&g_wsum[b], wv);
}
__global__ void k_pool(const int* __restrict__ batch) {
    int n = blockIdx.x;
    int d = threadIdx.x;
    if (d >= HH) return;
    int b = batch[n];
    float alpha = g_w[n] / g_wsum[b];
    atomicAdd(&g_pooled[b * HH + d], alpha * g_h[n * HH + d]);
}

// ================= FC via fp16 mma.sync m16n8k16 (native HMMA path) =================
// out[4096,50000] = pooled @ W_fc + b_fc  (fp16 inputs, fp32 accumulate)
// CTA: N-tile 128 cols, 16 M-tiles of 128 rows. grid (391, 2).
// Bs[n][k] halves (128 x 120, transposed for .col B) resident for whole K.
// As[r][k] halves (128 x 120) reloaded per M-tile (half2 packed stores).
// Warp grid 2x4; warp tile 64x32: 4x4 m16n8k16 MMAs per 16-wide k-step,
// 7 k-steps (K padded 100 -> 112 with zeros). Stride 120 halves = 60 words:
// 60*g mod 32 spans all banks -> conflict-free fragment loads.
#define FKH 120
#define FC_SMEM_H (128 * FKH * 2 * 2 + 512)   /* 61952 bytes */

__global__ void __launch_bounds__(256)
k_fc(const float* __restrict__ pooled, const float* __restrict__ W,
     const float* __restrict__ bias, float* __restrict__ C) {
    extern __shared__ __align__(16) char smraw[];
    __half*   BsH  = (__half*)smraw;                       // [128][FKH]
    uint32_t* Bs32 = (uint32_t*)smraw;                     // word view, stride 60
    uint32_t* As32 = (uint32_t*)(smraw + 128 * FKH * 2);   // word view, stride 60
    float*    biasS = (float*)(smraw + 2 * 128 * FKH * 2); // [128]
    int tid = threadIdx.x;
    int lane = tid & 31, wid = tid >> 5;
    int n0 = blockIdx.x * 128;
    int m_begin = blockIdx.y * 16;

    // zero both half tiles (covers K-pad cols and out-of-range N rows)
    for (int i = tid; i < 2 * 128 * (FKH / 2); i += 256) ((uint32_t*)smraw)[i] = 0u;
    if (tid < 128) biasS[tid] = (n0 + tid < VV) ? bias[n0 + tid] : 0.f;
    __syncthreads();

    // load B panel: W[k][n] -> BsH[n][k], coalesced over n, fp32 -> fp16
    for (int i = tid; i < HH * 128; i += 256) {
        int k = i >> 7, n = i & 127;
        int gn = n0 + n;
        if (gn < VV) BsH[n * FKH + k] = __float2half_rn(W[(size_t)k * VV + gn]);
    }

    int wm = wid >> 2, wn = wid & 3;    // warp tile: rows wm*64, cols wn*32
    int g = lane >> 2, tg = lane & 3;

    for (int it = 0; it < 16; it++) {
        int m0 = (m_begin + it) * 128;
        // A tile: half2-packed stores, 2 floats -> 1 word; 128 rows x 50 pairs
        for (int p = tid; p < 128 * (HH / 2); p += 256) {
            int r = p / (HH / 2), kp = p - r * (HH / 2);
            float2 v = *(const float2*)&pooled[(size_t)(m0 + r) * HH + 2 * kp];
            __half2 h2 = __floats2half2_rn(v.x, v.y);
            As32[r * (FKH / 2) + kp] = *(uint32_t*)&h2;
        }
        __syncthreads();

        float acc[4][4][4];
#pragma unroll
        for (int mi = 0; mi < 4; mi++)
#pragma unroll
            for (int ni = 0; ni < 4; ni++)
#pragma unroll
                for (int j = 0; j < 4; j++) acc[mi][ni][j] = 0.f;

#pragma unroll
        for (int ks = 0; ks < 7; ks++) {
            int kw = ks * 8;                 // word offset of this k-step
            uint32_t af[4][4], bf[4][2];
#pragma unroll
            for (int mi = 0; mi < 4; mi++) {
                int r0 = wm * 64 + mi * 16 + g;
                const uint32_t* ap = &As32[r0 * 60 + kw + tg];
                af[mi][0] = ap[0];                  // (g,   k 2tg..2tg+1)
                af[mi][1] = ap[8 * 60];             // (g+8, k 2tg..2tg+1)
                af[mi][2] = ap[4];                  // (g,   k 2tg+8..+9)
                af[mi][3] = ap[8 * 60 + 4];         // (g+8, k 2tg+8..+9)
            }
#pragma unroll
            for (int ni = 0; ni < 4; ni++) {
                int nb = wn * 32 + ni * 8 + g;
                const uint32_t* bp = &Bs32[nb * 60 + kw + tg];
                bf[ni][0] = bp[0];                  // (k 2tg..+1,  n)
                bf[ni][1] = bp[4];                  // (k 2tg+8..9, n)
            }
#pragma unroll
            for (int mi = 0; mi < 4; mi++)
#pragma unroll
                for (int ni = 0; ni < 4; ni++)
                    mma_16n8k16_f16(acc[mi][ni], af[mi], bf[ni]);
        }

        // epilogue: c0/c1 at (row, 2tg), c2/c3 at (row+8, 2tg)
#pragma unroll
        for (int mi = 0; mi < 4; mi++) {
            int r = m0 + wm * 64 + mi * 16 + g;
            size_t rb0 = (size_t)r * VV;
            size_t rb1 = (size_t)(r + 8) * VV;
#pragma unroll
            for (int ni = 0; ni < 4; ni++) {
                int cn = wn * 32 + ni * 8 + 2 * tg;
                int gn = n0 + cn;
                if (gn < VV) {   // VV even, gn even -> pair fully in range
                    float bx = biasS[cn], by = biasS[cn + 1];
                    *(float2*)&C[rb0 + gn] = make_float2(acc[mi][ni][0] + bx,
                                                         acc[mi][ni][1] + by);
                    *(float2*)&C[rb1 + gn] = make_float2(acc[mi][ni][2] + bx,
                                                         acc[mi][ni][3] + by);
                }
            }
        }
        __syncthreads();
    }
}

// ---------------- launch ----------------
extern "C" void kernel_launch(void* const* d_in, const int* in_sizes, int n_in,
                              void* d_out, int out_size) {
    const float* price    = (const float*)d_in[0];
    const int*   category = (const int*)d_in[1];
    const int*   sub      = (const int*)d_in[2];
    const int*   elem     = (const int*)d_in[3];
    const int*   brand    = (const int*)d_in[4];
    const int*   pid      = (const int*)d_in[5];
    const int*   eidx     = (const int*)d_in[6];
    const int*   batch    = (const int*)d_in[7];
    const float* ecat     = (const float*)d_in[8];
    const float* esub     = (const float*)d_in[9];
    const float* eelem    = (const float*)d_in[10];
    const float* ebrand   = (const float*)d_in[11];
    const float* eitem    = (const float*)d_in[12];
    const float* W_msg    = (const float*)d_in[13];
    const float* b_msg    = (const float*)d_in[14];
    const float* W_ih     = (const float*)d_in[15];
    const float* W_hh     = (const float*)d_in[16];
    const float* b_ih     = (const float*)d_in[17];
    const float* b_hh     = (const float*)d_in[18];
    const float* W_last   = (const float*)d_in[19];
    const float* b_last   = (const float*)d_in[20];
    const float* W_g1     = (const float*)d_in[21];
    const float* b_g1     = (const float*)d_in[22];
    const float* W_g2     = (const float*)d_in[23];
    const float* b_g2     = (const float*)d_in[24];
    const float* W_fc     = (const float*)d_in[25];
    const float* b_fc     = (const float*)d_in[26];
    float* out = (float*)d_out;

    float *p_x, *p_xl, *p_h, *p_msg, *p_gi, *p_gh, *p_last, *p_g1, *p_pooled;
    cudaGetSymbolAddress((void**)&p_x,      g_x);
    cudaGetSymbolAddress((void**)&p_xl,     g_xl);
    cudaGetSymbolAddress((void**)&p_h,      g_h);
    cudaGetSymbolAddress((void**)&p_msg,    g_msg);
    cudaGetSymbolAddress((void**)&p_gi,     g_gi);
    cudaGetSymbolAddress((void**)&p_gh,     g_gh);
    cudaGetSymbolAddress((void**)&p_last,   g_last);
    cudaGetSymbolAddress((void**)&p_g1,     g_g1);
    cudaGetSymbolAddress((void**)&p_pooled, g_pooled);

    cudaFuncSetAttribute(k_fc, cudaFuncAttributeMaxDynamicSharedMemorySize, FC_SMEM_H);

    // init scratch
    k_init_small<<<(NN + 255) / 256, 256>>>();
    k_zero_big<<<(NN * HH + 255) / 256, 256>>>();

    // node features
    k_gather_x<<<NN, 352>>>(price, category, sub, elem, brand, pid,
                            ecat, esub, eelem, ebrand, eitem);

    // h0 = x @ W_msg + b_msg
    {
        dim3 g((HH + 63) / 64, (NN + 127) / 128);
        k_sgemm<<<g, 256>>>(p_x, W_msg, b_msg, p_h, NN, HH, FIN, 0);
    }

    // degrees
    k_deg<<<(EE + 255) / 256, 256>>>(eidx);
    k_dinv<<<(NN + 255) / 256, 256>>>();

    // mean aggregation
    k_scatter<<<EE, 128>>>(eidx);
    k_scale_msg<<<(NN * HH + 255) / 256, 256>>>();

    // GRU gates
    {
        dim3 g((3 * HH + 63) / 64, (NN + 127) / 128);
        k_sgemm<<<g, 256>>>(p_msg, W_ih, b_ih, p_gi, NN, 3 * HH, HH, 0);
        k_sgemm<<<g, 256>>>(p_h,   W_hh, b_hh, p_gh, NN, 3 * HH, HH, 0);
    }
    k_gru<<<(NN * HH + 255) / 256, 256>>>();

    // last node per session
    k_lastidx<<<(NN + 255) / 256, 256>>>(batch);
    k_gather_xl<<<SS, 352>>>();
    {
        dim3 g((HH + 63) / 64, (SS + 127) / 128);
        k_sgemm<<<g, 256>>>(p_xl, W_last, b_last, p_last, SS, HH, FIN, 0);
    }
    k_addlast<<<(NN * HH + 255) / 256, 256>>>(batch);

    // attention gate MLP
    {
        dim3 g((HH + 63) / 64, (NN + 127) / 128);
        k_sgemm<<<g, 256>>>(p_h, W_g1, b_g1, p_g1, NN, HH, HH, 1);
    }
    k_gate<<<(NN * 32 + 255) / 256, 256>>>(W_g2, b_g2, batch);
    k_softw<<<(NN + 255) / 256, 256>>>(batch);
    k_pool<<<NN, 128>>>(batch);

    // final scoring: fp16 mma.sync m16n8k16
    {
        dim3 g((VV + 127) / 128, 2);
        k_fc<<<g, 256, FC_SMEM_H>>>(p_pooled, W_fc, b_fc, out);
    }
}